// round 2
// baseline (speedup 1.0000x reference)
#include <cuda_runtime.h>
#include <math.h>

#define NQ 4
#define NL 3
#define NG (NL * NQ)

// ---------------------------------------------------------------------------
// Precomputed batch-invariant data (written by prep kernel, read by main).
// g_rot4[2g]   = (r00.r, r00.i, r01.r, r01.i)
// g_rot4[2g+1] = (r10.r, r10.i, r11.r, r11.i)
// g_scale[g]   = scaling[l, q] * pi
// ---------------------------------------------------------------------------
__device__ float4 g_rot4[NG * 2];
__device__ float  g_scale[NG];

struct C2 { float r, i; };

__device__ __forceinline__ C2 cmul(const C2 a, const C2 b) {
    C2 o;
    o.r = fmaf(a.r, b.r, -(a.i * b.i));
    o.i = fmaf(a.r, b.i,   a.i * b.r);
    return o;
}

// a*b + c*d (complex), 8 FMA-class ops
__device__ __forceinline__ C2 cfma2(const C2 a, const C2 b, const C2 c, const C2 d) {
    C2 o;
    o.r = fmaf(a.r, b.r, fmaf(-a.i, b.i, fmaf(c.r, d.r, -(c.i * d.i))));
    o.i = fmaf(a.r, b.i, fmaf( a.i, b.r, fmaf(c.r, d.i,   c.i * d.r)));
    return o;
}

__device__ __forceinline__ float fast_tanh(float v) {
    // tanh(x) = 1 - 2/(e^{2x} + 1); MUFU.EX2 + fast rcp, ~1e-7 abs err in range
    float e = __expf(2.0f * v);
    return 1.0f - __fdividef(2.0f, e + 1.0f);
}

// ---------------------------------------------------------------------------
// Prep kernel: 12 Rot(phi, theta, omega) matrices + scaled encoding factors.
// Rot = RZ(omega) @ RY(theta) @ RZ(phi):
//   r00 =  cos(t/2) e^{-i(p+o)/2}   r01 = -sin(t/2) e^{+i(p-o)/2}
//   r10 =  sin(t/2) e^{-i(p-o)/2}   r11 =  cos(t/2) e^{+i(p+o)/2}
// ---------------------------------------------------------------------------
__global__ void prep_kernel(const float* __restrict__ w, const float* __restrict__ sc) {
    int g = threadIdx.x;
    if (g < NG) {
        float phi = w[3 * g + 0];
        float th  = w[3 * g + 1];
        float om  = w[3 * g + 2];
        float ct, st, cp, sp, cm, sm;
        sincosf(0.5f * th, &st, &ct);
        sincosf(0.5f * (phi + om), &sp, &cp);
        sincosf(0.5f * (phi - om), &sm, &cm);
        g_rot4[2 * g + 0] = make_float4(ct * cp, -ct * sp, -st * cm, -st * sm);
        g_rot4[2 * g + 1] = make_float4(st * cm, -st * sm,  ct * cp,  ct * sp);
        g_scale[g] = sc[g] * 3.14159265358979323846f;
    }
}

// ---------------------------------------------------------------------------
// Build fused per-(layer,qubit) unitary U = Rot @ diag(e^{-ia/4}, e^{+ia/4}) @ RY(a)
// where a = tanh(x_q) * scale * pi (tanh already applied in tq[]).
// Only ONE __sincosf (quarter angle); half-angle derived via double-angle
// identities: sin(a/2) = 2 sq cq,  cos(a/2) = 1 - 2 sq^2.
// ---------------------------------------------------------------------------
template <int Q>
__device__ __forceinline__ void build_u(int l, const float* tq,
                                        C2& u00, C2& u01, C2& u10, C2& u11) {
    int g = l * NQ + Q;
    float ang = tq[Q] * g_scale[g];
    float sq, cq;
    __sincosf(0.25f * ang, &sq, &cq);          // RZ quarter-angle phase
    float sh = 2.0f * sq * cq;                 // sin(ang/2)
    float ch = fmaf(-2.0f * sq, sq, 1.0f);     // cos(ang/2)
    float4 ra = g_rot4[2 * g + 0];
    float4 rb = g_rot4[2 * g + 1];
    C2 r00 = {ra.x, ra.y}, r01 = {ra.z, ra.w};
    C2 r10 = {rb.x, rb.y}, r11 = {rb.z, rb.w};
    C2 qc = {cq, -sq};   // e^{-i a/4}
    C2 qp = {cq,  sq};   // e^{+i a/4}
    C2 d00 = cmul(r00, qc), d01 = cmul(r01, qp);
    C2 d10 = cmul(r10, qc), d11 = cmul(r11, qp);
    // U = D @ [[ch, -sh], [sh, ch]]
    u00.r = fmaf(ch, d00.r,  sh * d01.r); u00.i = fmaf(ch, d00.i,  sh * d01.i);
    u01.r = fmaf(ch, d01.r, -sh * d00.r); u01.i = fmaf(ch, d01.i, -sh * d00.i);
    u10.r = fmaf(ch, d10.r,  sh * d11.r); u10.i = fmaf(ch, d10.i,  sh * d11.i);
    u11.r = fmaf(ch, d11.r, -sh * d10.r); u11.i = fmaf(ch, d11.i, -sh * d10.i);
}

// Amplitude index: i = b0*8 + b1*4 + b2*2 + b3 (qubit q -> bit mask 8>>q).
template <int M>
__device__ __forceinline__ void apply_gate(C2* s, C2 u00, C2 u01, C2 u10, C2 u11) {
#pragma unroll
    for (int i = 0; i < 16; i++) {
        if ((i & M) == 0) {
            C2 a0 = s[i], a1 = s[i | M];
            s[i]     = cfma2(u00, a0, u01, a1);
            s[i | M] = cfma2(u10, a0, u11, a1);
        }
    }
}

template <int MC, int MT>
__device__ __forceinline__ void cnot(C2* s) {
#pragma unroll
    for (int i = 0; i < 16; i++) {
        if ((i & MC) && !(i & MT)) {
            C2 tmp = s[i]; s[i] = s[i | MT]; s[i | MT] = tmp;
        }
    }
}

__device__ __forceinline__ void cnot_ring(C2* s) {
    cnot<8, 4>(s);   // CNOT(0,1)
    cnot<4, 2>(s);   // CNOT(1,2)
    cnot<2, 1>(s);   // CNOT(2,3)
    cnot<1, 8>(s);   // CNOT(3,0)
}

template <int Q>
__device__ __forceinline__ void apply_fused(int l, const float* tq, C2* s) {
    C2 u00, u01, u10, u11;
    build_u<Q>(l, tq, u00, u01, u10, u11);
    apply_gate<(8 >> Q)>(s, u00, u01, u10, u11);
}

__global__ __launch_bounds__(256)
void qsim_kernel(const float* __restrict__ x, float* __restrict__ out, int B) {
    int b = blockIdx.x * blockDim.x + threadIdx.x;
    if (b >= B) return;

    float4 xv = __ldg(reinterpret_cast<const float4*>(x) + b);
    float tq[NQ];
    tq[0] = fast_tanh(xv.x);
    tq[1] = fast_tanh(xv.y);
    tq[2] = fast_tanh(xv.z);
    tq[3] = fast_tanh(xv.w);

    C2 s[16];

    // ---- Layer 0: state is |0000>, so only column 0 of each U matters.
    // State = tensor product of the 4 first columns, then CNOT ring.
    {
        C2 c0[NQ], c1[NQ];  // (u00, u10) per qubit
        {
            C2 u00, u01, u10, u11;
            build_u<0>(0, tq, u00, u01, u10, u11); c0[0] = u00; c1[0] = u10;
            build_u<1>(0, tq, u00, u01, u10, u11); c0[1] = u00; c1[1] = u10;
            build_u<2>(0, tq, u00, u01, u10, u11); c0[2] = u00; c1[2] = u10;
            build_u<3>(0, tq, u00, u01, u10, u11); c0[3] = u00; c1[3] = u10;
        }
        C2 t01[4], t23[4];
        t01[0] = cmul(c0[0], c0[1]); t01[1] = cmul(c0[0], c1[1]);
        t01[2] = cmul(c1[0], c0[1]); t01[3] = cmul(c1[0], c1[1]);
        t23[0] = cmul(c0[2], c0[3]); t23[1] = cmul(c0[2], c1[3]);
        t23[2] = cmul(c1[2], c0[3]); t23[3] = cmul(c1[2], c1[3]);
#pragma unroll
        for (int i = 0; i < 16; i++) s[i] = cmul(t01[i >> 2], t23[i & 3]);
        cnot_ring(s);
    }

    // ---- Layers 1..2: full fused gates + CNOT ring.
#pragma unroll
    for (int l = 1; l < NL; l++) {
        apply_fused<0>(l, tq, s);
        apply_fused<1>(l, tq, s);
        apply_fused<2>(l, tq, s);
        apply_fused<3>(l, tq, s);
        cnot_ring(s);
    }

    // ---- Expectation values <Z_w> = sum_i |s_i|^2 * (-1)^{bit_w(i)}
    float p[16];
#pragma unroll
    for (int i = 0; i < 16; i++) p[i] = fmaf(s[i].r, s[i].r, s[i].i * s[i].i);

    float z0 = 0.f, z1 = 0.f, z2 = 0.f, z3 = 0.f;
#pragma unroll
    for (int i = 0; i < 16; i++) {
        z0 += (i & 8) ? -p[i] : p[i];
        z1 += (i & 4) ? -p[i] : p[i];
        z2 += (i & 2) ? -p[i] : p[i];
        z3 += (i & 1) ? -p[i] : p[i];
    }

    float4 o = make_float4(z0, z1, z2, z3);
    reinterpret_cast<float4*>(out)[b] = o;
}

extern "C" void kernel_launch(void* const* d_in, const int* in_sizes, int n_in,
                              void* d_out, int out_size) {
    const float* x  = (const float*)d_in[0];   // [B, 4]
    const float* w  = (const float*)d_in[1];   // [3, 4, 3]
    const float* sc = (const float*)d_in[2];   // [3, 4]
    float* out = (float*)d_out;                // [B, 4]
    int B = in_sizes[0] / NQ;

    prep_kernel<<<1, 32>>>(w, sc);
    int threads = 256;
    int blocks = (B + threads - 1) / threads;
    qsim_kernel<<<blocks, threads>>>(x, out, B);
}

// round 5
// speedup vs baseline: 1.0566x; 1.0566x over previous
#include <cuda_runtime.h>
#include <math.h>

#define NQ 4
#define NL 3
#define NG (NL * NQ)

// ---------------------------------------------------------------------------
// Batch-invariant data written by prep kernel.
// g_rotp[g*8 + k] = k-th Rot-matrix scalar of gate g, DUPLICATED {v, v} so the
//   main kernel's LDG.128 lands two packed-f32x2 registers directly.
//   order k: r00.r, r00.i, r01.r, r01.i, r10.r, r10.i, r11.r, r11.i
// g_scale4[g] = scaling[l,q] * pi * 0.25  (quarter-angle factor)
// ---------------------------------------------------------------------------
__device__ __align__(16) float2 g_rotp[NG * 8];
__device__ float g_scale4[NG];

// ---------------------------------------------------------------------------
// Packed f32x2 primitives (Blackwell FFMA2 path — PTX-only, ptxas won't emit)
// ---------------------------------------------------------------------------
typedef unsigned long long f2;

__device__ __forceinline__ f2 pack2(float lo, float hi) {
    f2 r; asm("mov.b64 %0, {%1, %2};" : "=l"(r) : "f"(lo), "f"(hi)); return r;
}
__device__ __forceinline__ void unpack2(f2 v, float& lo, float& hi) {
    asm("mov.b64 {%0, %1}, %2;" : "=f"(lo), "=f"(hi) : "l"(v));
}
__device__ __forceinline__ f2 fma2(f2 a, f2 b, f2 c) {
    f2 d; asm("fma.rn.f32x2 %0, %1, %2, %3;" : "=l"(d) : "l"(a), "l"(b), "l"(c)); return d;
}
__device__ __forceinline__ f2 mul2(f2 a, f2 b) {
    f2 d; asm("mul.rn.f32x2 %0, %1, %2;" : "=l"(d) : "l"(a), "l"(b)); return d;
}
__device__ __forceinline__ f2 add2(f2 a, f2 b) {
    f2 d; asm("add.rn.f32x2 %0, %1, %2;" : "=l"(d) : "l"(a), "l"(b)); return d;
}

struct Cp { f2 r, i; };  // packed complex: lane0 = sample A, lane1 = sample B

// (a*b) complex, packed; NEG1 = packed {-1,-1}
__device__ __forceinline__ Cp cmulp(Cp a, Cp b, f2 NEG1) {
    Cp o;
    f2 t = mul2(a.i, b.i);
    o.r = fma2(a.r, b.r, mul2(t, NEG1));
    o.i = fma2(a.i, b.r, mul2(a.r, b.i));
    return o;
}

__device__ __forceinline__ float fast_tanh(float v) {
    float e = __expf(2.0f * v);
    return 1.0f - __fdividef(2.0f, e + 1.0f);
}

// ---------------------------------------------------------------------------
// Prep kernel: Rot(phi, theta, omega) = RZ(omega) RY(theta) RZ(phi)
// ---------------------------------------------------------------------------
__global__ void prep_kernel(const float* __restrict__ w, const float* __restrict__ sc) {
    int g = threadIdx.x;
    if (g < NG) {
        float phi = w[3 * g + 0];
        float th  = w[3 * g + 1];
        float om  = w[3 * g + 2];
        float ct, st, cp, sp, cm, sm;
        sincosf(0.5f * th, &st, &ct);
        sincosf(0.5f * (phi + om), &sp, &cp);
        sincosf(0.5f * (phi - om), &sm, &cm);
        float e[8];
        e[0] =  ct * cp;  e[1] = -ct * sp;   // r00
        e[2] = -st * cm;  e[3] = -st * sm;   // r01
        e[4] =  st * cm;  e[5] = -st * sm;   // r10
        e[6] =  ct * cp;  e[7] =  ct * sp;   // r11
#pragma unroll
        for (int k = 0; k < 8; k++) g_rotp[g * 8 + k] = make_float2(e[k], e[k]);
        g_scale4[g] = sc[g] * (3.14159265358979323846f * 0.25f);
    }
}

// ---------------------------------------------------------------------------
// Build fused U = Rot @ RZ(ang/2) @ RY(ang), packed over 2 samples.
// ang = t * scale * pi; sincos at ang/4; sh=sin(ang/2)=2 sq cq, ch=1-2 sq^2.
// ---------------------------------------------------------------------------
__device__ __forceinline__ void build_u_p(int g, float tA, float tB,
                                          f2 ONE, f2 M2, f2 NEG1,
                                          Cp& u00, Cp& u01, Cp& u10, Cp& u11) {
    float s4 = g_scale4[g];
    float sA, cA, sB, cB;
    __sincosf(tA * s4, &sA, &cA);
    __sincosf(tB * s4, &sB, &cB);
    f2 sq = pack2(sA, sB), cq = pack2(cA, cB);

    const ulonglong2* rp = reinterpret_cast<const ulonglong2*>(g_rotp) + g * 4;
    ulonglong2 e0 = rp[0], e1 = rp[1], e2 = rp[2], e3 = rp[3];
    Cp r00 = {e0.x, e0.y}, r01 = {e1.x, e1.y};
    Cp r10 = {e2.x, e2.y}, r11 = {e3.x, e3.y};

    f2 nsq = mul2(sq, NEG1);
    // D = Rot @ diag(e^{-i a/4}, e^{+i a/4})
    Cp d00, d01, d10, d11;
    d00.r = fma2(r00.i, sq,  mul2(r00.r, cq));
    d00.i = fma2(r00.r, nsq, mul2(r00.i, cq));
    d10.r = fma2(r10.i, sq,  mul2(r10.r, cq));
    d10.i = fma2(r10.r, nsq, mul2(r10.i, cq));
    d01.r = fma2(r01.i, nsq, mul2(r01.r, cq));
    d01.i = fma2(r01.r, sq,  mul2(r01.i, cq));
    d11.r = fma2(r11.i, nsq, mul2(r11.r, cq));
    d11.i = fma2(r11.r, sq,  mul2(r11.i, cq));

    f2 t  = mul2(sq, cq);
    f2 sh = add2(t, t);                      // sin(ang/2)
    f2 ch = fma2(mul2(sq, sq), M2, ONE);     // cos(ang/2)
    f2 nsh = mul2(sh, NEG1);
    // U = D @ [[ch, -sh], [sh, ch]]
    u00.r = fma2(sh, d01.r, mul2(ch, d00.r));
    u00.i = fma2(sh, d01.i, mul2(ch, d00.i));
    u01.r = fma2(nsh, d00.r, mul2(ch, d01.r));
    u01.i = fma2(nsh, d00.i, mul2(ch, d01.i));
    u10.r = fma2(sh, d11.r, mul2(ch, d10.r));
    u10.i = fma2(sh, d11.i, mul2(ch, d10.i));
    u11.r = fma2(nsh, d10.r, mul2(ch, d11.r));
    u11.i = fma2(nsh, d10.i, mul2(ch, d11.i));
}

// Amplitude index: i = b0*8 + b1*4 + b2*2 + b3 (qubit q -> mask 8>>q).
template <int M>
__device__ __forceinline__ void apply_gate_p(Cp* s, Cp u00, Cp u01, Cp u10, Cp u11,
                                             f2 NEG1) {
    f2 n00 = mul2(u00.i, NEG1), n01 = mul2(u01.i, NEG1);
    f2 n10 = mul2(u10.i, NEG1), n11 = mul2(u11.i, NEG1);
#pragma unroll
    for (int i = 0; i < 16; i++) {
        if ((i & M) == 0) {
            Cp a0 = s[i], a1 = s[i | M];
            f2 r0 = mul2(u00.r, a0.r); r0 = fma2(n00, a0.i, r0);
            r0 = fma2(u01.r, a1.r, r0); r0 = fma2(n01, a1.i, r0);
            f2 i0 = mul2(u00.r, a0.i); i0 = fma2(u00.i, a0.r, i0);
            i0 = fma2(u01.r, a1.i, i0); i0 = fma2(u01.i, a1.r, i0);
            f2 r1 = mul2(u10.r, a0.r); r1 = fma2(n10, a0.i, r1);
            r1 = fma2(u11.r, a1.r, r1); r1 = fma2(n11, a1.i, r1);
            f2 i1 = mul2(u10.r, a0.i); i1 = fma2(u10.i, a0.r, i1);
            i1 = fma2(u11.r, a1.i, i1); i1 = fma2(u11.i, a1.r, i1);
            s[i].r = r0; s[i].i = i0;
            s[i | M].r = r1; s[i | M].i = i1;
        }
    }
}

template <int MC, int MT>
__device__ __forceinline__ void cnotp(Cp* s) {
#pragma unroll
    for (int i = 0; i < 16; i++) {
        if ((i & MC) && !(i & MT)) {
            Cp tmp = s[i]; s[i] = s[i | MT]; s[i | MT] = tmp;
        }
    }
}

__device__ __forceinline__ void cnot_ring_p(Cp* s) {
    cnotp<8, 4>(s);
    cnotp<4, 2>(s);
    cnotp<2, 1>(s);
    cnotp<1, 8>(s);
}

__global__ __launch_bounds__(128)
void qsim_kernel(const float* __restrict__ x, float* __restrict__ out, int B2) {
    int t = blockIdx.x * blockDim.x + threadIdx.x;
    if (t >= B2) return;

    const f2 ONE  = pack2(1.0f, 1.0f);
    const f2 M2   = pack2(-2.0f, -2.0f);
    const f2 NEG1 = pack2(-1.0f, -1.0f);

    const float4* x4 = reinterpret_cast<const float4*>(x);
    float4 xa = x4[2 * t], xb = x4[2 * t + 1];
    float tqA[NQ] = {fast_tanh(xa.x), fast_tanh(xa.y), fast_tanh(xa.z), fast_tanh(xa.w)};
    float tqB[NQ] = {fast_tanh(xb.x), fast_tanh(xb.y), fast_tanh(xb.z), fast_tanh(xb.w)};

    Cp s[16];

    // ---- Layer 0: |0000> -> product state from column 0 of each U, then ring
    {
        Cp c0[NQ], c1[NQ];
#pragma unroll
        for (int q = 0; q < NQ; q++) {
            Cp u00, u01, u10, u11;
            build_u_p(q, tqA[q], tqB[q], ONE, M2, NEG1, u00, u01, u10, u11);
            c0[q] = u00; c1[q] = u10;
        }
        Cp t01[4], t23[4];
        t01[0] = cmulp(c0[0], c0[1], NEG1); t01[1] = cmulp(c0[0], c1[1], NEG1);
        t01[2] = cmulp(c1[0], c0[1], NEG1); t01[3] = cmulp(c1[0], c1[1], NEG1);
        t23[0] = cmulp(c0[2], c0[3], NEG1); t23[1] = cmulp(c0[2], c1[3], NEG1);
        t23[2] = cmulp(c1[2], c0[3], NEG1); t23[3] = cmulp(c1[2], c1[3], NEG1);
#pragma unroll
        for (int i = 0; i < 16; i++) s[i] = cmulp(t01[i >> 2], t23[i & 3], NEG1);
        cnot_ring_p(s);
    }

    // ---- Layers 1..2
#pragma unroll
    for (int l = 1; l < NL; l++) {
#pragma unroll
        for (int q = 0; q < NQ; q++) {
            Cp u00, u01, u10, u11;
            build_u_p(l * NQ + q, tqA[q], tqB[q], ONE, M2, NEG1, u00, u01, u10, u11);
            if (q == 0) apply_gate_p<8>(s, u00, u01, u10, u11, NEG1);
            if (q == 1) apply_gate_p<4>(s, u00, u01, u10, u11, NEG1);
            if (q == 2) apply_gate_p<2>(s, u00, u01, u10, u11, NEG1);
            if (q == 3) apply_gate_p<1>(s, u00, u01, u10, u11, NEG1);
        }
        cnot_ring_p(s);
    }

    // ---- Probabilities and <Z_w>, shared partial sums
    f2 p[16];
#pragma unroll
    for (int i = 0; i < 16; i++) p[i] = fma2(s[i].r, s[i].r, mul2(s[i].i, s[i].i));

    f2 a[8], bb[4], c[2];
#pragma unroll
    for (int k = 0; k < 8; k++) a[k] = add2(p[2 * k], p[2 * k + 1]);
#pragma unroll
    for (int k = 0; k < 4; k++) bb[k] = add2(a[2 * k], a[2 * k + 1]);
    c[0] = add2(bb[0], bb[1]); c[1] = add2(bb[2], bb[3]);
    f2 tot = add2(c[0], c[1]);

    // z_w = tot - 2 * (sum of p where bit_w set)
    f2 s0 = c[1];                                            // mask 8
    f2 s1 = add2(bb[1], bb[3]);                              // mask 4
    f2 s2 = add2(add2(a[1], a[3]), add2(a[5], a[7]));        // mask 2
    f2 s3 = add2(add2(add2(p[1], p[3]), add2(p[5], p[7])),
                 add2(add2(p[9], p[11]), add2(p[13], p[15])));   // mask 1
    f2 z0 = fma2(M2, s0, tot);
    f2 z1 = fma2(M2, s1, tot);
    f2 z2 = fma2(M2, s2, tot);
    f2 z3 = fma2(M2, s3, tot);

    float z0A, z0B, z1A, z1B, z2A, z2B, z3A, z3B;
    unpack2(z0, z0A, z0B); unpack2(z1, z1A, z1B);
    unpack2(z2, z2A, z2B); unpack2(z3, z3A, z3B);

    float4* o4 = reinterpret_cast<float4*>(out);
    o4[2 * t]     = make_float4(z0A, z1A, z2A, z3A);
    o4[2 * t + 1] = make_float4(z0B, z1B, z2B, z3B);
}

extern "C" void kernel_launch(void* const* d_in, const int* in_sizes, int n_in,
                              void* d_out, int out_size) {
    const float* x  = (const float*)d_in[0];   // [B, 4]
    const float* w  = (const float*)d_in[1];   // [3, 4, 3]
    const float* sc = (const float*)d_in[2];   // [3, 4]
    float* out = (float*)d_out;                // [B, 4]
    int B = in_sizes[0] / NQ;
    int B2 = B / 2;                            // 2 samples per thread

    prep_kernel<<<1, 32>>>(w, sc);
    int threads = 128;
    int blocks = (B2 + threads - 1) / threads;
    qsim_kernel<<<blocks, threads>>>(x, out, B2);
}

// round 6
// speedup vs baseline: 1.1271x; 1.0667x over previous
#include <cuda_runtime.h>
#include <math.h>

#define NQ 4
#define NL 3
#define NG (NL * NQ)

// ---------------------------------------------------------------------------
// Batch-invariant data written by prep kernel.
// g_rotp[g*8 + k] = k-th Rot-matrix scalar of gate g, DUPLICATED {v, v} so the
//   main kernel's LDG.128 lands two packed-f32x2 registers directly.
//   order k: r00.r, r00.i, r01.r, r01.i, r10.r, r10.i, r11.r, r11.i
// g_scaleh[g] = scaling[l,q] * pi * 0.5  (half-angle factor)
// ---------------------------------------------------------------------------
__device__ __align__(16) float2 g_rotp[NG * 8];
__device__ float g_scaleh[NG];

// ---------------------------------------------------------------------------
// Packed f32x2 primitives (Blackwell FFMA2 path — PTX-only, ptxas won't emit)
// ---------------------------------------------------------------------------
typedef unsigned long long f2;

__device__ __forceinline__ f2 pack2(float lo, float hi) {
    f2 r; asm("mov.b64 %0, {%1, %2};" : "=l"(r) : "f"(lo), "f"(hi)); return r;
}
__device__ __forceinline__ void unpack2(f2 v, float& lo, float& hi) {
    asm("mov.b64 {%0, %1}, %2;" : "=f"(lo), "=f"(hi) : "l"(v));
}
__device__ __forceinline__ f2 fma2(f2 a, f2 b, f2 c) {
    f2 d; asm("fma.rn.f32x2 %0, %1, %2, %3;" : "=l"(d) : "l"(a), "l"(b), "l"(c)); return d;
}
__device__ __forceinline__ f2 mul2(f2 a, f2 b) {
    f2 d; asm("mul.rn.f32x2 %0, %1, %2;" : "=l"(d) : "l"(a), "l"(b)); return d;
}
__device__ __forceinline__ f2 add2(f2 a, f2 b) {
    f2 d; asm("add.rn.f32x2 %0, %1, %2;" : "=l"(d) : "l"(a), "l"(b)); return d;
}

struct Cp { f2 r, i; };  // packed complex: lane0 = sample A, lane1 = sample B

// (a*b) complex, packed; NEG1 = packed {-1,-1}
__device__ __forceinline__ Cp cmulp(Cp a, Cp b, f2 NEG1) {
    Cp o;
    f2 t = mul2(a.i, b.i);
    o.r = fma2(a.r, b.r, mul2(t, NEG1));
    o.i = fma2(a.i, b.r, mul2(a.r, b.i));
    return o;
}

__device__ __forceinline__ float fast_tanh(float v) {
    float e = __expf(2.0f * v);
    return 1.0f - __fdividef(2.0f, e + 1.0f);
}

// ---------------------------------------------------------------------------
// Prep kernel: Rot(phi, theta, omega) = RZ(omega) RY(theta) RZ(phi)
// ---------------------------------------------------------------------------
__global__ void prep_kernel(const float* __restrict__ w, const float* __restrict__ sc) {
    int g = threadIdx.x;
    if (g < NG) {
        float phi = w[3 * g + 0];
        float th  = w[3 * g + 1];
        float om  = w[3 * g + 2];
        float ct, st, cp, sp, cm, sm;
        sincosf(0.5f * th, &st, &ct);
        sincosf(0.5f * (phi + om), &sp, &cp);
        sincosf(0.5f * (phi - om), &sm, &cm);
        float e[8];
        e[0] =  ct * cp;  e[1] = -ct * sp;   // r00
        e[2] = -st * cm;  e[3] = -st * sm;   // r01
        e[4] =  st * cm;  e[5] = -st * sm;   // r10
        e[6] =  ct * cp;  e[7] =  ct * sp;   // r11
#pragma unroll
        for (int k = 0; k < 8; k++) g_rotp[g * 8 + k] = make_float2(e[k], e[k]);
        g_scaleh[g] = sc[g] * (3.14159265358979323846f * 0.5f);
    }
}

// ---------------------------------------------------------------------------
// Fused gate up to GLOBAL PHASE (probabilities invariant):
//   U' = Rot @ diag(1, p) @ RY(ang),  p = e^{i ang/2} = (ch, sh)
// where (sh, ch) = sincos(ang/2) serve BOTH the RZ phase and the RY rotation.
// D col0 = Rot col0 (free); D col1 = Rot col1 * p; U = D @ [[ch,-sh],[sh,ch]].
// 26 packed ops, one __sincosf per sample.
// ---------------------------------------------------------------------------
__device__ __forceinline__ void build_u_p(int g, float tA, float tB, f2 NEG1,
                                          Cp& u00, Cp& u01, Cp& u10, Cp& u11) {
    float sH = g_scaleh[g];
    float sA, cA, sB, cB;
    __sincosf(tA * sH, &sA, &cA);
    __sincosf(tB * sH, &sB, &cB);
    f2 sh = pack2(sA, sB), ch = pack2(cA, cB);
    f2 nsh = mul2(sh, NEG1);

    const ulonglong2* rp = reinterpret_cast<const ulonglong2*>(g_rotp) + g * 4;
    ulonglong2 e0 = rp[0], e1 = rp[1], e2 = rp[2], e3 = rp[3];
    Cp r00 = {e0.x, e0.y}, r01 = {e1.x, e1.y};
    Cp r10 = {e2.x, e2.y}, r11 = {e3.x, e3.y};

    // D col1 = Rot col1 * p
    Cp d01, d11;
    d01.r = fma2(r01.i, nsh, mul2(r01.r, ch));
    d01.i = fma2(r01.i, ch,  mul2(r01.r, sh));
    d11.r = fma2(r11.i, nsh, mul2(r11.r, ch));
    d11.i = fma2(r11.i, ch,  mul2(r11.r, sh));

    // U = [ (r00, d01) ; (r10, d11) ] @ [[ch, -sh], [sh, ch]]
    u00.r = fma2(sh, d01.r, mul2(ch, r00.r));
    u00.i = fma2(sh, d01.i, mul2(ch, r00.i));
    u01.r = fma2(nsh, r00.r, mul2(ch, d01.r));
    u01.i = fma2(nsh, r00.i, mul2(ch, d01.i));
    u10.r = fma2(sh, d11.r, mul2(ch, r10.r));
    u10.i = fma2(sh, d11.i, mul2(ch, r10.i));
    u11.r = fma2(nsh, r10.r, mul2(ch, d11.r));
    u11.i = fma2(nsh, r10.i, mul2(ch, d11.i));
}

// Column-0-only variant for layer 0 (state |0000>): 17 packed ops.
__device__ __forceinline__ void build_u_col0(int g, float tA, float tB, f2 NEG1,
                                             Cp& u00, Cp& u10) {
    float sH = g_scaleh[g];
    float sA, cA, sB, cB;
    __sincosf(tA * sH, &sA, &cA);
    __sincosf(tB * sH, &sB, &cB);
    f2 sh = pack2(sA, sB), ch = pack2(cA, cB);
    f2 nsh = mul2(sh, NEG1);

    const ulonglong2* rp = reinterpret_cast<const ulonglong2*>(g_rotp) + g * 4;
    ulonglong2 e0 = rp[0], e1 = rp[1], e2 = rp[2], e3 = rp[3];
    Cp r00 = {e0.x, e0.y}, r01 = {e1.x, e1.y};
    Cp r10 = {e2.x, e2.y}, r11 = {e3.x, e3.y};

    Cp d01, d11;
    d01.r = fma2(r01.i, nsh, mul2(r01.r, ch));
    d01.i = fma2(r01.i, ch,  mul2(r01.r, sh));
    d11.r = fma2(r11.i, nsh, mul2(r11.r, ch));
    d11.i = fma2(r11.i, ch,  mul2(r11.r, sh));

    u00.r = fma2(sh, d01.r, mul2(ch, r00.r));
    u00.i = fma2(sh, d01.i, mul2(ch, r00.i));
    u10.r = fma2(sh, d11.r, mul2(ch, r10.r));
    u10.i = fma2(sh, d11.i, mul2(ch, r10.i));
}

// Amplitude index: i = b0*8 + b1*4 + b2*2 + b3 (qubit q -> mask 8>>q).
template <int M>
__device__ __forceinline__ void apply_gate_p(Cp* s, Cp u00, Cp u01, Cp u10, Cp u11,
                                             f2 NEG1) {
    f2 n00 = mul2(u00.i, NEG1), n01 = mul2(u01.i, NEG1);
    f2 n10 = mul2(u10.i, NEG1), n11 = mul2(u11.i, NEG1);
#pragma unroll
    for (int i = 0; i < 16; i++) {
        if ((i & M) == 0) {
            Cp a0 = s[i], a1 = s[i | M];
            f2 r0 = mul2(u00.r, a0.r); r0 = fma2(n00, a0.i, r0);
            r0 = fma2(u01.r, a1.r, r0); r0 = fma2(n01, a1.i, r0);
            f2 i0 = mul2(u00.r, a0.i); i0 = fma2(u00.i, a0.r, i0);
            i0 = fma2(u01.r, a1.i, i0); i0 = fma2(u01.i, a1.r, i0);
            f2 r1 = mul2(u10.r, a0.r); r1 = fma2(n10, a0.i, r1);
            r1 = fma2(u11.r, a1.r, r1); r1 = fma2(n11, a1.i, r1);
            f2 i1 = mul2(u10.r, a0.i); i1 = fma2(u10.i, a0.r, i1);
            i1 = fma2(u11.r, a1.i, i1); i1 = fma2(u11.i, a1.r, i1);
            s[i].r = r0; s[i].i = i0;
            s[i | M].r = r1; s[i | M].i = i1;
        }
    }
}

template <int MC, int MT>
__device__ __forceinline__ void cnotp(Cp* s) {
#pragma unroll
    for (int i = 0; i < 16; i++) {
        if ((i & MC) && !(i & MT)) {
            Cp tmp = s[i]; s[i] = s[i | MT]; s[i | MT] = tmp;
        }
    }
}

__device__ __forceinline__ void cnot_ring_p(Cp* s) {
    cnotp<8, 4>(s);
    cnotp<4, 2>(s);
    cnotp<2, 1>(s);
    cnotp<1, 8>(s);
}

__global__ __launch_bounds__(128)
void qsim_kernel(const float* __restrict__ x, float* __restrict__ out, int B2) {
    int t = blockIdx.x * blockDim.x + threadIdx.x;
    if (t >= B2) return;

    const f2 M2   = pack2(-2.0f, -2.0f);
    const f2 NEG1 = pack2(-1.0f, -1.0f);

    const float4* x4 = reinterpret_cast<const float4*>(x);
    float4 xa = x4[2 * t], xb = x4[2 * t + 1];
    float tqA[NQ] = {fast_tanh(xa.x), fast_tanh(xa.y), fast_tanh(xa.z), fast_tanh(xa.w)};
    float tqB[NQ] = {fast_tanh(xb.x), fast_tanh(xb.y), fast_tanh(xb.z), fast_tanh(xb.w)};

    Cp s[16];

    // ---- Layer 0: |0000> -> product state from column 0 of each U, then ring
    {
        Cp c0[NQ], c1[NQ];
#pragma unroll
        for (int q = 0; q < NQ; q++)
            build_u_col0(q, tqA[q], tqB[q], NEG1, c0[q], c1[q]);

        Cp t01[4], t23[4];
        t01[0] = cmulp(c0[0], c0[1], NEG1); t01[1] = cmulp(c0[0], c1[1], NEG1);
        t01[2] = cmulp(c1[0], c0[1], NEG1); t01[3] = cmulp(c1[0], c1[1], NEG1);
        t23[0] = cmulp(c0[2], c0[3], NEG1); t23[1] = cmulp(c0[2], c1[3], NEG1);
        t23[2] = cmulp(c1[2], c0[3], NEG1); t23[3] = cmulp(c1[2], c1[3], NEG1);
#pragma unroll
        for (int i = 0; i < 16; i++) s[i] = cmulp(t01[i >> 2], t23[i & 3], NEG1);
        cnot_ring_p(s);
    }

    // ---- Layers 1..2
#pragma unroll
    for (int l = 1; l < NL; l++) {
#pragma unroll
        for (int q = 0; q < NQ; q++) {
            Cp u00, u01, u10, u11;
            build_u_p(l * NQ + q, tqA[q], tqB[q], NEG1, u00, u01, u10, u11);
            if (q == 0) apply_gate_p<8>(s, u00, u01, u10, u11, NEG1);
            if (q == 1) apply_gate_p<4>(s, u00, u01, u10, u11, NEG1);
            if (q == 2) apply_gate_p<2>(s, u00, u01, u10, u11, NEG1);
            if (q == 3) apply_gate_p<1>(s, u00, u01, u10, u11, NEG1);
        }
        cnot_ring_p(s);
    }

    // ---- Probabilities and <Z_w>, shared partial sums
    f2 p[16];
#pragma unroll
    for (int i = 0; i < 16; i++) p[i] = fma2(s[i].r, s[i].r, mul2(s[i].i, s[i].i));

    f2 a[8], bb[4], c[2];
#pragma unroll
    for (int k = 0; k < 8; k++) a[k] = add2(p[2 * k], p[2 * k + 1]);
#pragma unroll
    for (int k = 0; k < 4; k++) bb[k] = add2(a[2 * k], a[2 * k + 1]);
    c[0] = add2(bb[0], bb[1]); c[1] = add2(bb[2], bb[3]);
    f2 tot = add2(c[0], c[1]);

    // z_w = tot - 2 * (sum of p where bit_w set)
    f2 s0 = c[1];                                            // mask 8
    f2 s1 = add2(bb[1], bb[3]);                              // mask 4
    f2 s2 = add2(add2(a[1], a[3]), add2(a[5], a[7]));        // mask 2
    f2 s3 = add2(add2(add2(p[1], p[3]), add2(p[5], p[7])),
                 add2(add2(p[9], p[11]), add2(p[13], p[15])));   // mask 1
    f2 z0 = fma2(M2, s0, tot);
    f2 z1 = fma2(M2, s1, tot);
    f2 z2 = fma2(M2, s2, tot);
    f2 z3 = fma2(M2, s3, tot);

    float z0A, z0B, z1A, z1B, z2A, z2B, z3A, z3B;
    unpack2(z0, z0A, z0B); unpack2(z1, z1A, z1B);
    unpack2(z2, z2A, z2B); unpack2(z3, z3A, z3B);

    float4* o4 = reinterpret_cast<float4*>(out);
    o4[2 * t]     = make_float4(z0A, z1A, z2A, z3A);
    o4[2 * t + 1] = make_float4(z0B, z1B, z2B, z3B);
}

extern "C" void kernel_launch(void* const* d_in, const int* in_sizes, int n_in,
                              void* d_out, int out_size) {
    const float* x  = (const float*)d_in[0];   // [B, 4]
    const float* w  = (const float*)d_in[1];   // [3, 4, 3]
    const float* sc = (const float*)d_in[2];   // [3, 4]
    float* out = (float*)d_out;                // [B, 4]
    int B = in_sizes[0] / NQ;
    int B2 = B / 2;                            // 2 samples per thread

    prep_kernel<<<1, 32>>>(w, sc);
    int threads = 128;
    int blocks = (B2 + threads - 1) / threads;
    qsim_kernel<<<blocks, threads>>>(x, out, B2);
}